// round 2
// baseline (speedup 1.0000x reference)
#include <cuda_runtime.h>
#include <cuda_bf16.h>
#include <cfloat>
#include <cstdint>

// Problem constants
#define B_   65536
#define I_   640     // input dim
#define L_   2560    // latent dim
#define K_   32      // top-k

// Encode GEMM tiling
#define TM   64
#define TN   128
#define TK   32
#define NTHR 256

// Scratch (device globals — no allocation allowed)
__device__ float g_WdT[(size_t)L_ * I_];          // [2560][640] transposed decoder
__device__ float g_topk_v[(size_t)B_ * K_];
__device__ int   g_topk_i[(size_t)B_ * K_];

// ---------------------------------------------------------------------------
// Kernel 0: transpose Wd [I_, L_] -> WdT [L_, I_]
// ---------------------------------------------------------------------------
__global__ void transpose_wd_kernel(const float* __restrict__ Wd) {
    __shared__ float tile[32][33];
    const int l0 = blockIdx.x * 32;   // latent dim tile
    const int i0 = blockIdx.y * 32;   // input dim tile
    const int tx = threadIdx.x;       // 0..31
    const int ty = threadIdx.y;       // 0..7
    #pragma unroll
    for (int r = ty; r < 32; r += 8)
        tile[r][tx] = Wd[(size_t)(i0 + r) * L_ + l0 + tx];
    __syncthreads();
    #pragma unroll
    for (int r = ty; r < 32; r += 8)
        g_WdT[(size_t)(l0 + r) * I_ + i0 + tx] = tile[tx][r];
}

// ---------------------------------------------------------------------------
// Kernel 1: fused encode GEMM + bias + streaming top-32 + sparse scatter
//   latents[b,l] = sum_i x[b,i] * We[l,i] + be[l]
//   block: 64 rows x all 2560 cols (in 20 tiles of 128), fp32 SGEMM
//   topk kept as sorted-descending (val, idx) lists in smem; tie-break:
//   equal value -> smaller index wins (matches jax.lax.top_k).
// ---------------------------------------------------------------------------
__global__ void __launch_bounds__(NTHR)
encode_topk_kernel(const float* __restrict__ x,
                   const float* __restrict__ We,
                   const float* __restrict__ be,
                   float* __restrict__ sparse_out /* [B_, L_] */) {
    extern __shared__ float smem[];
    float* As = smem;                     // [TK][TM]         2048 f
    float* Bs = As + TK * TM;             // [TK][TN]         4096 f
    float* Cs = Bs + TK * TN;             // [TM][129]        8256 f
    float* hv = Cs + TM * 129;            // [TM][33]         2112 f
    int*   hi = (int*)(hv + TM * 33);     // [TM][33]         2112 i

    const int tid  = threadIdx.x;
    const int row0 = blockIdx.x * TM;
    const int tx = tid & 15;   // col group 0..15 (8 cols each)
    const int ty = tid >> 4;   // row group 0..15 (4 rows each)

    // init topk lists
    for (int idx = tid; idx < TM * K_; idx += NTHR) {
        int m = idx / K_, k = idx % K_;
        hv[m * 33 + k] = -FLT_MAX;
        hi[m * 33 + k] = 0x7fffffff;
    }
    __syncthreads();

    for (int ct = 0; ct < L_ / TN; ++ct) {
        const int col0 = ct * TN;
        float acc[4][8];
        #pragma unroll
        for (int i = 0; i < 4; ++i)
            #pragma unroll
            for (int j = 0; j < 8; ++j) acc[i][j] = 0.0f;

        for (int k0 = 0; k0 < I_; k0 += TK) {
            // Load A tile: x[row0..row0+63][k0..k0+31]  (512 float4)
            #pragma unroll
            for (int it = 0; it < (TM * TK / 4) / NTHR; ++it) {
                int i  = tid + it * NTHR;
                int m  = i >> 3;          // / (TK/4)
                int kq = i & 7;
                float4 v = *(const float4*)(x + (size_t)(row0 + m) * I_ + k0 + kq * 4);
                As[(kq * 4 + 0) * TM + m] = v.x;
                As[(kq * 4 + 1) * TM + m] = v.y;
                As[(kq * 4 + 2) * TM + m] = v.z;
                As[(kq * 4 + 3) * TM + m] = v.w;
            }
            // Load B tile: We[col0..col0+127][k0..k0+31]  (1024 float4)
            #pragma unroll
            for (int it = 0; it < (TN * TK / 4) / NTHR; ++it) {
                int i  = tid + it * NTHR;
                int n  = i >> 3;
                int kq = i & 7;
                float4 v = *(const float4*)(We + (size_t)(col0 + n) * I_ + k0 + kq * 4);
                Bs[(kq * 4 + 0) * TN + n] = v.x;
                Bs[(kq * 4 + 1) * TN + n] = v.y;
                Bs[(kq * 4 + 2) * TN + n] = v.z;
                Bs[(kq * 4 + 3) * TN + n] = v.w;
            }
            __syncthreads();

            #pragma unroll
            for (int kk = 0; kk < TK; ++kk) {
                float4 a4  = *(const float4*)&As[kk * TM + ty * 4];
                float4 b40 = *(const float4*)&Bs[kk * TN + tx * 8];
                float4 b41 = *(const float4*)&Bs[kk * TN + tx * 8 + 4];
                float a[4] = {a4.x, a4.y, a4.z, a4.w};
                float b[8] = {b40.x, b40.y, b40.z, b40.w, b41.x, b41.y, b41.z, b41.w};
                #pragma unroll
                for (int i = 0; i < 4; ++i)
                    #pragma unroll
                    for (int j = 0; j < 8; ++j)
                        acc[i][j] = fmaf(a[i], b[j], acc[i][j]);
            }
            __syncthreads();
        }

        // epilogue: add bias, stage tile to smem
        #pragma unroll
        for (int j = 0; j < 8; ++j) {
            float bj = __ldg(&be[col0 + tx * 8 + j]);
            #pragma unroll
            for (int i = 0; i < 4; ++i)
                Cs[(ty * 4 + i) * 129 + tx * 8 + j] = acc[i][j] + bj;
        }
        __syncthreads();

        // streaming top-32 update: one thread per row
        if (tid < TM) {
            const int m = tid;
            float minv = hv[m * 33 + (K_ - 1)];
            int   mini = hi[m * 33 + (K_ - 1)];
            for (int n = 0; n < TN; ++n) {
                float v = Cs[m * 129 + n];
                int col = col0 + n;
                bool beats = (v > minv) || (v == minv && col < mini);
                if (beats) {
                    int p = K_ - 1;
                    while (p > 0) {
                        float pv = hv[m * 33 + p - 1];
                        int   pi = hi[m * 33 + p - 1];
                        bool b2 = (v > pv) || (v == pv && col < pi);
                        if (!b2) break;
                        hv[m * 33 + p] = pv;
                        hi[m * 33 + p] = pi;
                        --p;
                    }
                    hv[m * 33 + p] = v;
                    hi[m * 33 + p] = col;
                    minv = hv[m * 33 + (K_ - 1)];
                    mini = hi[m * 33 + (K_ - 1)];
                }
            }
        }
        __syncthreads();
    }

    // zero-fill the 64x2560 sparse region (float4 stores, coalesced)
    {
        float4 z = make_float4(0.f, 0.f, 0.f, 0.f);
        float4* sp = (float4*)(sparse_out + (size_t)row0 * L_);
        const int total = TM * L_ / 4;  // 40960
        for (int i = tid; i < total; i += NTHR) sp[i] = z;
    }
    __syncthreads();

    // scatter topk values; also publish (val, idx) for the decode kernel
    if (tid < TM) {
        const int m = tid;
        const size_t brow = (size_t)(row0 + m);
        #pragma unroll
        for (int k = 0; k < K_; ++k) {
            float v = hv[m * 33 + k];
            int   c = hi[m * 33 + k];
            sparse_out[brow * L_ + c] = v;
            g_topk_v[brow * K_ + k] = v;
            g_topk_i[brow * K_ + k] = c;
        }
    }
}

// ---------------------------------------------------------------------------
// Kernel 2: sparse decode.  recon[b,i] = bd[i] + sum_k v_k * WdT[idx_k, i]
//   one block per row, 128 threads x 5 outputs
// ---------------------------------------------------------------------------
__global__ void __launch_bounds__(128)
decode_kernel(const float* __restrict__ bd, float* __restrict__ recon) {
    __shared__ float sv[K_];
    __shared__ int   si[K_];
    const int b = blockIdx.x;
    const int t = threadIdx.x;
    if (t < K_) {
        sv[t] = g_topk_v[(size_t)b * K_ + t];
        si[t] = g_topk_i[(size_t)b * K_ + t];
    }
    __syncthreads();

    float acc[5];
    #pragma unroll
    for (int j = 0; j < 5; ++j) acc[j] = __ldg(&bd[t + j * 128]);

    #pragma unroll
    for (int k = 0; k < K_; ++k) {
        float v = sv[k];
        const float* col = g_WdT + (size_t)si[k] * I_;
        #pragma unroll
        for (int j = 0; j < 5; ++j)
            acc[j] = fmaf(v, __ldg(&col[t + j * 128]), acc[j]);
    }
    #pragma unroll
    for (int j = 0; j < 5; ++j)
        recon[(size_t)b * I_ + t + j * 128] = acc[j];
}

// ---------------------------------------------------------------------------
// Launch
// ---------------------------------------------------------------------------
extern "C" void kernel_launch(void* const* d_in, const int* in_sizes, int n_in,
                              void* d_out, int out_size) {
    const float* x  = (const float*)d_in[0];   // [65536, 640]
    const float* We = (const float*)d_in[1];   // [2560, 640]
    const float* be = (const float*)d_in[2];   // [2560]
    const float* Wd = (const float*)d_in[3];   // [640, 2560]
    const float* bd = (const float*)d_in[4];   // [640]

    float* recon  = (float*)d_out;                        // [B_, I_]
    float* sparse = (float*)d_out + (size_t)B_ * I_;      // [B_, L_]

    const int smem_bytes =
        (TK * TM + TK * TN + TM * 129 + TM * 33) * (int)sizeof(float)
        + TM * 33 * (int)sizeof(int);
    cudaFuncSetAttribute(encode_topk_kernel,
                         cudaFuncAttributeMaxDynamicSharedMemorySize, smem_bytes);

    transpose_wd_kernel<<<dim3(L_ / 32, I_ / 32), dim3(32, 8)>>>(Wd);
    encode_topk_kernel<<<B_ / TM, NTHR, smem_bytes>>>(x, We, be, sparse);
    decode_kernel<<<B_, 128>>>(bd, recon);
}